// round 1
// baseline (speedup 1.0000x reference)
#include <cuda_runtime.h>
#include <cuda_bf16.h>
#include <cstdint>

#define N_ATOMS 8000
#define N_PAIRS 80000
#define NF 32
#define N_DIST 16
#define N_COMP 4
#define ACOLS 512              // n_dist * nf_out, layout [o*16+d]
#define GN_EPS 1e-5f

// Scratch (device globals: no allocation allowed)
__device__ __align__(16) float g_A[(size_t)N_ATOMS * ACOLS];
__device__ __align__(16) float g_self[(size_t)N_ATOMS * NF];
__device__ int g_seg[N_ATOMS + 1];

// ---------------------------------------------------------------------------
// Kernel 1: segment starts via lower_bound on sorted pair_first
// ---------------------------------------------------------------------------
__global__ void k_seg(const int* __restrict__ pf) {
    int i = blockIdx.x * blockDim.x + threadIdx.x;
    if (i > N_ATOMS) return;
    int lo = 0, hi = N_PAIRS;
    while (lo < hi) {
        int mid = (lo + hi) >> 1;
        if (pf[mid] < i) lo = mid + 1; else hi = mid;
    }
    g_seg[i] = lo;
}

// ---------------------------------------------------------------------------
// Kernel 2: A[a, o*16+d] = sum_f feat[a,f] * W[d,o,f]   (+ self-interaction)
// 544 threads: cols 0..511 -> interaction weights, cols 512..543 -> selfint
// 16 atoms per block, weights held in registers, feat via broadcast LDS.128
// ---------------------------------------------------------------------------
__global__ void __launch_bounds__(544) k_prep(
    const float* __restrict__ feat,
    const float* __restrict__ Wint,     // (16,32,32) d,o,f
    const float* __restrict__ sw,       // (32,32) o,f
    const float* __restrict__ sb)       // (32,)
{
    __shared__ __align__(16) float fsh[16 * NF];
    const int tid = threadIdx.x;
    const int a0 = blockIdx.x * 16;

    if (tid < 16 * NF) fsh[tid] = feat[(size_t)a0 * NF + tid];

    float w[NF];
    float bias = 0.f;
    const float* wp;
    if (tid < ACOLS) {
        int d = tid & 15, o = tid >> 4;
        wp = Wint + d * (NF * NF) + o * NF;
    } else {
        int o = tid - ACOLS;
        wp = sw + o * NF;
        bias = sb[o];
    }
#pragma unroll
    for (int f = 0; f < NF; ++f) w[f] = wp[f];
    __syncthreads();

#pragma unroll 4
    for (int a = 0; a < 16; ++a) {
        const float4* fr = (const float4*)(fsh + a * NF);
        float acc = bias;
#pragma unroll
        for (int q = 0; q < NF / 4; ++q) {
            float4 v = fr[q];
            acc = fmaf(v.x, w[4 * q + 0], acc);
            acc = fmaf(v.y, w[4 * q + 1], acc);
            acc = fmaf(v.z, w[4 * q + 2], acc);
            acc = fmaf(v.w, w[4 * q + 3], acc);
        }
        if (tid < ACOLS) g_A[(size_t)(a0 + a) * ACOLS + tid] = acc;
        else             g_self[(size_t)(a0 + a) * NF + (tid - ACOLS)] = acc;
    }
}

// ---------------------------------------------------------------------------
// Kernel 3: fused per-atom warp kernel.
// lane = output channel o. Per pair: sense (lanes 0..15 own d), gather A row,
// shfl-dot, rhat accumulation. Then invariants -> GroupNorm -> mixing + self.
// ---------------------------------------------------------------------------
__device__ __forceinline__ float warp_sum(float v) {
#pragma unroll
    for (int off = 16; off; off >>= 1)
        v += __shfl_xor_sync(0xffffffffu, v, off);
    return v;
}

__global__ void __launch_bounds__(256) k_main(
    const float* __restrict__ rhats,    // (P,4)
    const float* __restrict__ dist,     // (P,)
    const float* __restrict__ mw,       // (32,2,32) flat (64,32)
    const float* __restrict__ gnw,      // (64,)
    const float* __restrict__ gnb,      // (64,)
    const float* __restrict__ mu,       // (16,)
    const float* __restrict__ sg,       // (16,)
    const int*   __restrict__ psec,     // (P,)
    float* __restrict__ out)            // (N,32)
{
    const int warp = threadIdx.x >> 5;
    const int lane = threadIdx.x & 31;
    const int a = blockIdx.x * 8 + warp;
    if (a >= N_ATOMS) return;

    const float mu_l  = mu[lane & 15];
    const float isg_l = 1.0f / sg[lane & 15];

    const int p0 = g_seg[a];
    const int p1 = g_seg[a + 1];

    float acc0 = 0.f, acc1 = 0.f, acc2 = 0.f, acc3 = 0.f;

    for (int p = p0; p < p1; ++p) {
        const float dd = dist[p];
        const int   j  = psec[p];
        const float4 rh = *(const float4*)(rhats + 4 * (size_t)p);

        // sensitivity: lanes 0..15 hold e_d for d = lane&15
        float t = (1.0f / dd - mu_l) * isg_l;
        float e = __expf(-0.5f * t * t);
        float cut = 0.f;
        if (dd < 6.5f) {
            float cc = cospif(dd * (0.5f / 6.5f));
            cut = cc * cc;
        }

        // gather A row: lane o reads A[j, o*16 .. o*16+15]  (4x LDG.128)
        const float4* Ar = (const float4*)(g_A + (size_t)j * ACOLS + (lane << 4));
        float4 v0 = Ar[0], v1 = Ar[1], v2 = Ar[2], v3 = Ar[3];
        float av[16];
        av[0]=v0.x; av[1]=v0.y; av[2]=v0.z; av[3]=v0.w;
        av[4]=v1.x; av[5]=v1.y; av[6]=v1.z; av[7]=v1.w;
        av[8]=v2.x; av[9]=v2.y; av[10]=v2.z; av[11]=v2.w;
        av[12]=v3.x; av[13]=v3.y; av[14]=v3.z; av[15]=v3.w;

        float dotv = 0.f;
#pragma unroll
        for (int d2 = 0; d2 < 16; ++d2)
            dotv = fmaf(__shfl_sync(0xffffffffu, e, d2), av[d2], dotv);

        const float wgt = cut * dotv;
        acc0 = fmaf(rh.x, wgt, acc0);
        acc1 = fmaf(rh.y, wgt, acc1);
        acc2 = fmaf(rh.z, wgt, acc2);
        acc3 = fmaf(rh.w, wgt, acc3);
    }

    // invariants: [l=0 scalar, |l=1 vector|^2]
    const float inv0 = acc0;
    const float inv1 = acc1 * acc1 + acc2 * acc2 + acc3 * acc3;

    // GroupNorm (two-pass, over the 32 lanes per group)
    const float m0 = warp_sum(inv0) * (1.f / 32.f);
    const float c0 = inv0 - m0;
    const float v0s = warp_sum(c0 * c0) * (1.f / 32.f);
    float xn0 = c0 * rsqrtf(v0s + GN_EPS);
    xn0 = fmaf(xn0, gnw[lane], gnb[lane]);

    const float m1 = warp_sum(inv1) * (1.f / 32.f);
    const float c1 = inv1 - m1;
    const float v1s = warp_sum(c1 * c1) * (1.f / 32.f);
    float xn1 = c1 * rsqrtf(v1s + GN_EPS);
    xn1 = fmaf(xn1, gnw[32 + lane], gnb[32 + lane]);

    // mixing: out[o] = sum_{oin,i} norm[oin,i] * MW[oin*2+i, o]   (+ self)
    float o_acc = g_self[(size_t)a * NF + lane];
#pragma unroll
    for (int oin = 0; oin < 32; ++oin) {
        const float n0 = __shfl_sync(0xffffffffu, xn0, oin);
        const float n1 = __shfl_sync(0xffffffffu, xn1, oin);
        o_acc = fmaf(n0, mw[(oin * 2 + 0) * NF + lane], o_acc);
        o_acc = fmaf(n1, mw[(oin * 2 + 1) * NF + lane], o_acc);
    }

    out[(size_t)a * NF + lane] = o_acc;
}

// ---------------------------------------------------------------------------
extern "C" void kernel_launch(void* const* d_in, const int* in_sizes, int n_in,
                              void* d_out, int out_size) {
    const float* in_features = (const float*)d_in[0];
    const float* tensor_rhats = (const float*)d_in[1];
    const float* dist_pairs = (const float*)d_in[2];
    const float* int_weights = (const float*)d_in[3];
    const float* selfint_w = (const float*)d_in[4];
    const float* selfint_b = (const float*)d_in[5];
    const float* mixing_weights = (const float*)d_in[6];
    const float* gn_weight = (const float*)d_in[7];
    const float* gn_bias = (const float*)d_in[8];
    const float* sens_mu = (const float*)d_in[9];
    const float* sens_sigma = (const float*)d_in[10];
    const int* pair_first = (const int*)d_in[11];
    const int* pair_second = (const int*)d_in[12];
    float* out = (float*)d_out;

    k_seg<<<(N_ATOMS + 1 + 255) / 256, 256>>>(pair_first);
    k_prep<<<N_ATOMS / 16, 544>>>(in_features, int_weights, selfint_w, selfint_b);
    k_main<<<N_ATOMS / 8, 256>>>(tensor_rhats, dist_pairs, mixing_weights,
                                 gn_weight, gn_bias, sens_mu, sens_sigma,
                                 pair_second, out);
}

// round 2
// speedup vs baseline: 1.2411x; 1.2411x over previous
#include <cuda_runtime.h>
#include <cuda_fp16.h>
#include <cstdint>

#define N_ATOMS 8000
#define N_PAIRS 80000
#define NF 32
#define N_DIST 16
#define ACOLS 512              // n_dist * nf_out, layout [o*16+d]
#define GN_EPS 1e-5f

// Scratch (device globals: no allocation allowed)
__device__ __align__(16) __half g_A[(size_t)N_ATOMS * ACOLS];   // fp16 A-table, 8 MB
__device__ __align__(16) float g_self[(size_t)N_ATOMS * NF];
__device__ int g_seg[N_ATOMS + 1];

// ---------------------------------------------------------------------------
// Kernel 1: segment starts via scatter on sorted pair_first (no dependent
// load chain -- replaces the 17-deep binary search).
// seg[a] = lower_bound(pf, a): thread p covers a in (pf[p-1], pf[p]].
// ---------------------------------------------------------------------------
__global__ void k_seg(const int* __restrict__ pf) {
    int p = blockIdx.x * blockDim.x + threadIdx.x;
    if (p >= N_PAIRS) return;
    int cur = pf[p];
    int prev = (p == 0) ? -1 : pf[p - 1];
    for (int a = prev + 1; a <= cur; ++a) g_seg[a] = p;
    if (p == N_PAIRS - 1)
        for (int a = cur + 1; a <= N_ATOMS; ++a) g_seg[a] = N_PAIRS;
}

// ---------------------------------------------------------------------------
// Kernel 2: A[a, o*16+d] = sum_f feat[a,f] * W[d,o,f]   (+ self-interaction)
// 544 threads: cols 0..511 -> interaction weights (fp16 out),
//              cols 512..543 -> selfint (fp32 out)
// ---------------------------------------------------------------------------
__global__ void __launch_bounds__(544) k_prep(
    const float* __restrict__ feat,
    const float* __restrict__ Wint,     // (16,32,32) d,o,f
    const float* __restrict__ sw,       // (32,32) o,f
    const float* __restrict__ sb)       // (32,)
{
    __shared__ __align__(16) float fsh[16 * NF];
    const int tid = threadIdx.x;
    const int a0 = blockIdx.x * 16;

    if (tid < 16 * NF) fsh[tid] = feat[(size_t)a0 * NF + tid];

    float w[NF];
    float bias = 0.f;
    const float* wp;
    if (tid < ACOLS) {
        int d = tid & 15, o = tid >> 4;
        wp = Wint + d * (NF * NF) + o * NF;
    } else {
        int o = tid - ACOLS;
        wp = sw + o * NF;
        bias = sb[o];
    }
#pragma unroll
    for (int f = 0; f < NF; ++f) w[f] = wp[f];
    __syncthreads();

#pragma unroll 4
    for (int a = 0; a < 16; ++a) {
        const float4* fr = (const float4*)(fsh + a * NF);
        float acc = bias;
#pragma unroll
        for (int q = 0; q < NF / 4; ++q) {
            float4 v = fr[q];
            acc = fmaf(v.x, w[4 * q + 0], acc);
            acc = fmaf(v.y, w[4 * q + 1], acc);
            acc = fmaf(v.z, w[4 * q + 2], acc);
            acc = fmaf(v.w, w[4 * q + 3], acc);
        }
        if (tid < ACOLS) g_A[(size_t)(a0 + a) * ACOLS + tid] = __float2half(acc);
        else             g_self[(size_t)(a0 + a) * NF + (tid - ACOLS)] = acc;
    }
}

// ---------------------------------------------------------------------------
// Kernel 3: fused per-atom warp kernel.
// lane = output channel o. Per pair: sense (lanes 0..15 own d), fp16 gather of
// A row (2x LDG.128, 32B/lane), shfl-broadcast dot, rhat accumulation.
// Then invariants -> GroupNorm -> mixing + self, all warp-level.
// ---------------------------------------------------------------------------
__device__ __forceinline__ float warp_sum(float v) {
#pragma unroll
    for (int off = 16; off; off >>= 1)
        v += __shfl_xor_sync(0xffffffffu, v, off);
    return v;
}

__global__ void __launch_bounds__(256) k_main(
    const float* __restrict__ rhats,    // (P,4)
    const float* __restrict__ dist,     // (P,)
    const float* __restrict__ mw,       // (32,2,32) flat (64,32)
    const float* __restrict__ gnw,      // (64,)
    const float* __restrict__ gnb,      // (64,)
    const float* __restrict__ mu,       // (16,)
    const float* __restrict__ sg,       // (16,)
    const int*   __restrict__ psec,     // (P,)
    float* __restrict__ out)            // (N,32)
{
    const int warp = threadIdx.x >> 5;
    const int lane = threadIdx.x & 31;
    const int a = blockIdx.x * 8 + warp;
    if (a >= N_ATOMS) return;

    const float mu_l  = mu[lane & 15];
    const float isg_l = 1.0f / sg[lane & 15];

    const int p0 = g_seg[a];
    const int p1 = g_seg[a + 1];

    float acc0 = 0.f, acc1 = 0.f, acc2 = 0.f, acc3 = 0.f;

    for (int p = p0; p < p1; ++p) {
        const float dd = dist[p];
        const int   j  = psec[p];
        const float4 rh = *(const float4*)(rhats + 4 * (size_t)p);

        // sensitivity: lanes 0..15 hold e_d for d = lane&15
        float t = (1.0f / dd - mu_l) * isg_l;
        float e = __expf(-0.5f * t * t);
        float cut = 0.f;
        if (dd < 6.5f) {
            float cc = cospif(dd * (0.5f / 6.5f));
            cut = cc * cc;
        }

        // gather A row (fp16): lane o reads A[j, o*16 .. o*16+15]  (2x LDG.128)
        const uint4* Ar = (const uint4*)(g_A + (size_t)j * ACOLS + (lane << 4));
        uint4 u0 = Ar[0], u1 = Ar[1];
        uint32_t wv[8] = {u0.x, u0.y, u0.z, u0.w, u1.x, u1.y, u1.z, u1.w};
        float av[16];
#pragma unroll
        for (int k = 0; k < 8; ++k) {
            float2 f2 = __half22float2(*reinterpret_cast<__half2*>(&wv[k]));
            av[2 * k]     = f2.x;
            av[2 * k + 1] = f2.y;
        }

        float dotv = 0.f;
#pragma unroll
        for (int d2 = 0; d2 < 16; ++d2)
            dotv = fmaf(__shfl_sync(0xffffffffu, e, d2), av[d2], dotv);

        const float wgt = cut * dotv;
        acc0 = fmaf(rh.x, wgt, acc0);
        acc1 = fmaf(rh.y, wgt, acc1);
        acc2 = fmaf(rh.z, wgt, acc2);
        acc3 = fmaf(rh.w, wgt, acc3);
    }

    // invariants: [l=0 scalar, |l=1 vector|^2]
    const float inv0 = acc0;
    const float inv1 = acc1 * acc1 + acc2 * acc2 + acc3 * acc3;

    // GroupNorm (two-pass, over the 32 lanes per group)
    const float m0 = warp_sum(inv0) * (1.f / 32.f);
    const float c0 = inv0 - m0;
    const float v0s = warp_sum(c0 * c0) * (1.f / 32.f);
    float xn0 = c0 * rsqrtf(v0s + GN_EPS);
    xn0 = fmaf(xn0, gnw[lane], gnb[lane]);

    const float m1 = warp_sum(inv1) * (1.f / 32.f);
    const float c1 = inv1 - m1;
    const float v1s = warp_sum(c1 * c1) * (1.f / 32.f);
    float xn1 = c1 * rsqrtf(v1s + GN_EPS);
    xn1 = fmaf(xn1, gnw[32 + lane], gnb[32 + lane]);

    // mixing: out[o] = sum_{oin,i} norm[oin,i] * MW[oin*2+i, o]   (+ self)
    float o_acc = g_self[(size_t)a * NF + lane];
#pragma unroll
    for (int oin = 0; oin < 32; ++oin) {
        const float n0 = __shfl_sync(0xffffffffu, xn0, oin);
        const float n1 = __shfl_sync(0xffffffffu, xn1, oin);
        o_acc = fmaf(n0, mw[(oin * 2 + 0) * NF + lane], o_acc);
        o_acc = fmaf(n1, mw[(oin * 2 + 1) * NF + lane], o_acc);
    }

    out[(size_t)a * NF + lane] = o_acc;
}

// ---------------------------------------------------------------------------
extern "C" void kernel_launch(void* const* d_in, const int* in_sizes, int n_in,
                              void* d_out, int out_size) {
    const float* in_features = (const float*)d_in[0];
    const float* tensor_rhats = (const float*)d_in[1];
    const float* dist_pairs = (const float*)d_in[2];
    const float* int_weights = (const float*)d_in[3];
    const float* selfint_w = (const float*)d_in[4];
    const float* selfint_b = (const float*)d_in[5];
    const float* mixing_weights = (const float*)d_in[6];
    const float* gn_weight = (const float*)d_in[7];
    const float* gn_bias = (const float*)d_in[8];
    const float* sens_mu = (const float*)d_in[9];
    const float* sens_sigma = (const float*)d_in[10];
    const int* pair_first = (const int*)d_in[11];
    const int* pair_second = (const int*)d_in[12];
    float* out = (float*)d_out;

    k_seg<<<(N_PAIRS + 255) / 256, 256>>>(pair_first);
    k_prep<<<N_ATOMS / 16, 544>>>(in_features, int_weights, selfint_w, selfint_b);
    k_main<<<N_ATOMS / 8, 256>>>(tensor_rhats, dist_pairs, mixing_weights,
                                 gn_weight, gn_bias, sens_mu, sens_sigma,
                                 pair_second, out);
}

// round 3
// speedup vs baseline: 1.7619x; 1.4196x over previous
#include <cuda_runtime.h>
#include <cuda_fp16.h>
#include <cstdint>

#define N_ATOMS 8000
#define N_PAIRS 80000
#define NF 32
#define GN_EPS 1e-5f

#define NB 296            // 2 CTAs/SM x 148 SMs: all resident in wave 1
#define NT 256
#define NWARPS_TOT (NB * 8)

// Scratch (device globals: no allocation allowed)
// A-table fp16 packed: A2[a*256 + q*32 + o] = half2( A[a,2q,o], A[a,2q+1,o] )
__device__ __align__(16) uint32_t g_A2[(size_t)N_ATOMS * 256];
__device__ __align__(16) float g_self[(size_t)N_ATOMS * NF];
__device__ int g_seg[N_ATOMS + 1];

// Grid barrier state: monotonic across launches (deterministic, no reset).
__device__ unsigned long long g_arrive = 0;
__device__ volatile unsigned long long g_release = 0;

__device__ __forceinline__ void grid_barrier() {
    __syncthreads();
    if (threadIdx.x == 0) {
        __threadfence();
        unsigned long long t = atomicAdd(&g_arrive, 1ULL) + 1ULL;
        unsigned long long target = ((t + NB - 1) / NB) * NB;
        if (t == target) {
            g_release = target;
        } else {
            while (g_release < target) __nanosleep(64);
        }
        __threadfence();
    }
    __syncthreads();
}

__device__ __forceinline__ float warp_sum(float v) {
#pragma unroll
    for (int off = 16; off; off >>= 1)
        v += __shfl_xor_sync(0xffffffffu, v, off);
    return v;
}

__device__ __forceinline__ void loadA(uint32_t A[8], int j, int lane) {
    const uint32_t* base = g_A2 + (size_t)j * 256 + lane;
#pragma unroll
    for (int q = 0; q < 8; ++q) A[q] = __ldg(base + q * 32);
}

__global__ void __launch_bounds__(NT, 2) k_fused(
    const float* __restrict__ feat,     // (N,32)
    const float* __restrict__ rhats,    // (P,4)
    const float* __restrict__ dist,     // (P,)
    const float* __restrict__ Wint,     // (16,32,32) d,o,f
    const float* __restrict__ sw,       // (32,32) o,f
    const float* __restrict__ sb,       // (32,)
    const float* __restrict__ mw,       // (64,32)
    const float* __restrict__ gnw,      // (64,)
    const float* __restrict__ gnb,      // (64,)
    const float* __restrict__ mu,       // (16,)
    const float* __restrict__ sg,       // (16,)
    const int*   __restrict__ pf,       // (P,)  sorted
    const int*   __restrict__ psec,     // (P,)
    float* __restrict__ out)            // (N,32)
{
    __shared__ __align__(16) float swT[NF * NF];   // transposed selfint weights
    __shared__ __align__(16) float fsh[8 * NF];    // feat staging for prep tiles

    const int tid  = threadIdx.x;
    const int bid  = blockIdx.x;
    const int lane = tid & 31;
    const int wid  = tid >> 5;
    const int gtid = bid * NT + tid;

    // ============================ PHASE A ===================================
    // A1: segment starts via scatter on sorted pair_first
    for (int p = gtid; p < N_PAIRS; p += NB * NT) {
        int cur  = pf[p];
        int prev = (p == 0) ? -1 : pf[p - 1];
        for (int a = prev + 1; a <= cur; ++a) g_seg[a] = p;
        if (p == N_PAIRS - 1)
            for (int a = cur + 1; a <= N_ATOMS; ++a) g_seg[a] = N_PAIRS;
    }

    // A2: stage transposed self-interaction weights, then compute g_self
    for (int i = tid; i < NF * NF; i += NT) {
        int o = i >> 5, f = i & 31;
        swT[f * NF + o] = sw[i];
    }
    __syncthreads();

    for (int idx = gtid; idx < N_ATOMS * NF; idx += NB * NT) {
        int a = idx >> 5, o = idx & 31;
        float s = sb[o];
        const float* fr = feat + (size_t)a * NF;
#pragma unroll
        for (int f = 0; f < NF; ++f)
            s = fmaf(fr[f], swT[f * NF + o], s);   // fr[f] warp-broadcast
        g_self[idx] = s;
    }

    // A3: A-table. thread t: o = lane, q = wid (0..7), covers d = {2q, 2q+1}.
    {
        const int q = wid, o = lane;
        float w0[NF], w1[NF];
        const float* wp0 = Wint + (2 * q) * (NF * NF) + o * NF;
        const float* wp1 = Wint + (2 * q + 1) * (NF * NF) + o * NF;
#pragma unroll
        for (int f = 0; f < NF; ++f) { w0[f] = wp0[f]; w1[f] = wp1[f]; }

        for (int tile = bid; tile < N_ATOMS / 8; tile += NB) {
            const int a0 = tile * 8;
            __syncthreads();
            fsh[tid] = feat[(size_t)a0 * NF + tid];
            __syncthreads();
#pragma unroll
            for (int k = 0; k < 8; ++k) {
                const float* fr = fsh + k * NF;
                float acc0 = 0.f, acc1 = 0.f;
#pragma unroll
                for (int f = 0; f < NF; ++f) {
                    float fv = fr[f];
                    acc0 = fmaf(fv, w0[f], acc0);
                    acc1 = fmaf(fv, w1[f], acc1);
                }
                __half2 h2 = __floats2half2_rn(acc0, acc1);
                g_A2[(size_t)(a0 + k) * 256 + q * 32 + o] =
                    *reinterpret_cast<uint32_t*>(&h2);
            }
        }
    }

    grid_barrier();

    // ============================ PHASE B ===================================
    // warp per atom: lane = output channel o
    const float mu_l  = mu[lane & 15];
    const float isg_l = 1.0f / sg[lane & 15];
    const int gwarp = bid * 8 + wid;

    for (int a = gwarp; a < N_ATOMS; a += NWARPS_TOT) {
        const int p0 = g_seg[a];
        const int n  = g_seg[a + 1] - p0;

        float acc0 = 0.f, acc1 = 0.f, acc2 = 0.f, acc3 = 0.f;

        if (n > 0) {
            // software pipeline: depth-2 psec, depth-1 A-row / scalars
            int jn = (n > 1) ? psec[p0 + 1] : 0;
            float  ddc = dist[p0];
            float4 rhc = *(const float4*)(rhats + 4 * (size_t)p0);
            uint32_t Ac[8];
            loadA(Ac, psec[p0], lane);

            for (int i = 0; i < n; ++i) {
                uint32_t An[8];
                if (i + 1 < n) loadA(An, jn, lane);        // jn loaded last iter
                int j2 = (i + 2 < n) ? psec[p0 + i + 2] : 0;
                float  ddn = 0.f;
                float4 rhn = make_float4(0.f, 0.f, 0.f, 0.f);
                if (i + 1 < n) {
                    ddn = dist[p0 + i + 1];
                    rhn = *(const float4*)(rhats + 4 * (size_t)(p0 + i + 1));
                }

                // sensitivity: lanes 0..15 hold e_d
                float t = (1.0f / ddc - mu_l) * isg_l;
                float e = __expf(-0.5f * t * t);
                float cut = 0.f;
                if (ddc < 6.5f) {
                    float cc = cospif(ddc * (0.5f / 6.5f));
                    cut = cc * cc;
                }

                float dotv = 0.f;
#pragma unroll
                for (int q = 0; q < 8; ++q) {
                    float2 f2 = __half22float2(*reinterpret_cast<__half2*>(&Ac[q]));
                    dotv = fmaf(__shfl_sync(0xffffffffu, e, 2 * q),     f2.x, dotv);
                    dotv = fmaf(__shfl_sync(0xffffffffu, e, 2 * q + 1), f2.y, dotv);
                }

                const float wgt = cut * dotv;
                acc0 = fmaf(rhc.x, wgt, acc0);
                acc1 = fmaf(rhc.y, wgt, acc1);
                acc2 = fmaf(rhc.z, wgt, acc2);
                acc3 = fmaf(rhc.w, wgt, acc3);

                // rotate pipeline
#pragma unroll
                for (int q = 0; q < 8; ++q) Ac[q] = An[q];
                jn = j2; ddc = ddn; rhc = rhn;
            }
        }

        // invariants
        const float inv0 = acc0;
        const float inv1 = acc1 * acc1 + acc2 * acc2 + acc3 * acc3;

        // GroupNorm over 32 lanes per group
        const float m0 = warp_sum(inv0) * (1.f / 32.f);
        const float c0 = inv0 - m0;
        const float v0s = warp_sum(c0 * c0) * (1.f / 32.f);
        float xn0 = c0 * rsqrtf(v0s + GN_EPS);
        xn0 = fmaf(xn0, gnw[lane], gnb[lane]);

        const float m1 = warp_sum(inv1) * (1.f / 32.f);
        const float c1 = inv1 - m1;
        const float v1s = warp_sum(c1 * c1) * (1.f / 32.f);
        float xn1 = c1 * rsqrtf(v1s + GN_EPS);
        xn1 = fmaf(xn1, gnw[32 + lane], gnb[32 + lane]);

        // mixing + self
        float o_acc = g_self[(size_t)a * NF + lane];
#pragma unroll
        for (int oin = 0; oin < 32; ++oin) {
            const float n0 = __shfl_sync(0xffffffffu, xn0, oin);
            const float n1 = __shfl_sync(0xffffffffu, xn1, oin);
            o_acc = fmaf(n0, mw[(oin * 2 + 0) * NF + lane], o_acc);
            o_acc = fmaf(n1, mw[(oin * 2 + 1) * NF + lane], o_acc);
        }
        out[(size_t)a * NF + lane] = o_acc;
    }
}

// ---------------------------------------------------------------------------
extern "C" void kernel_launch(void* const* d_in, const int* in_sizes, int n_in,
                              void* d_out, int out_size) {
    const float* in_features = (const float*)d_in[0];
    const float* tensor_rhats = (const float*)d_in[1];
    const float* dist_pairs = (const float*)d_in[2];
    const float* int_weights = (const float*)d_in[3];
    const float* selfint_w = (const float*)d_in[4];
    const float* selfint_b = (const float*)d_in[5];
    const float* mixing_weights = (const float*)d_in[6];
    const float* gn_weight = (const float*)d_in[7];
    const float* gn_bias = (const float*)d_in[8];
    const float* sens_mu = (const float*)d_in[9];
    const float* sens_sigma = (const float*)d_in[10];
    const int* pair_first = (const int*)d_in[11];
    const int* pair_second = (const int*)d_in[12];
    float* out = (float*)d_out;

    k_fused<<<NB, NT>>>(in_features, tensor_rhats, dist_pairs, int_weights,
                        selfint_w, selfint_b, mixing_weights, gn_weight,
                        gn_bias, sens_mu, sens_sigma, pair_first, pair_second,
                        out);
}

// round 4
// speedup vs baseline: 1.7630x; 1.0006x over previous
#include <cuda_runtime.h>
#include <cuda_fp16.h>
#include <cstdint>

#define N_ATOMS 8000
#define N_PAIRS 80000
#define NF 32
#define GN_EPS 1e-5f

#define NB 444            // 3 CTAs/SM x 148 SMs: all resident in wave 1
#define NT 256
#define NWARPS_TOT (NB * 8)

// Scratch (device globals: no allocation allowed)
// A-table fp16 packed: A2[a*256 + q*32 + o] = half2( A[a,2q,o], A[a,2q+1,o] )
__device__ __align__(16) uint32_t g_A2[(size_t)N_ATOMS * 256];
// transposed fp16 weights: WT2[f*256 + q*32 + o] = half2(W[2q,o,f], W[2q+1,o,f])
__device__ __align__(16) uint32_t g_WT2[32 * 256];
// sense table fp32: sense[p*16 + d] = cut(d_p) * exp(...)
__device__ __align__(16) float g_sense[(size_t)N_PAIRS * 16];
__device__ __align__(16) float g_self[(size_t)N_ATOMS * NF];
__device__ int g_seg[N_ATOMS + 1];

// Grid barrier state: monotonic across launches (deterministic, no reset).
__device__ unsigned long long g_arrive = 0;
__device__ volatile unsigned long long g_release = 0;

__device__ __forceinline__ void grid_barrier() {
    __syncthreads();
    if (threadIdx.x == 0) {
        __threadfence();
        unsigned long long t = atomicAdd(&g_arrive, 1ULL) + 1ULL;
        unsigned long long target = ((t + NB - 1) / NB) * NB;
        if (t == target) {
            g_release = target;
        } else {
            while (g_release < target) __nanosleep(64);
        }
        __threadfence();
    }
    __syncthreads();
}

__device__ __forceinline__ float warp_sum(float v) {
#pragma unroll
    for (int off = 16; off; off >>= 1)
        v += __shfl_xor_sync(0xffffffffu, v, off);
    return v;
}

__device__ __forceinline__ void loadA(uint32_t A[8], int j, int lane) {
    const uint32_t* base = g_A2 + (size_t)j * 256 + lane;
#pragma unroll
    for (int q = 0; q < 8; ++q) A[q] = __ldg(base + q * 32);
}

__global__ void __launch_bounds__(NT, 3) k_fused(
    const float* __restrict__ feat,     // (N,32)
    const float* __restrict__ rhats,    // (P,4)
    const float* __restrict__ dist,     // (P,)
    const float* __restrict__ Wint,     // (16,32,32) d,o,f
    const float* __restrict__ sw,       // (32,32) o,f
    const float* __restrict__ sb,       // (32,)
    const float* __restrict__ mw,       // (64,32)
    const float* __restrict__ gnw,      // (64,)
    const float* __restrict__ gnb,      // (64,)
    const float* __restrict__ mu,       // (16,)
    const float* __restrict__ sg,       // (16,)
    const int*   __restrict__ pf,       // (P,)  sorted
    const int*   __restrict__ psec,     // (P,)
    float* __restrict__ out)            // (N,32)
{
    __shared__ __align__(16) float swT[NF * NF];   // transposed selfint weights
    __shared__ __align__(16) float fsh[8 * NF];    // feat staging for A3 tiles

    const int tid  = threadIdx.x;
    const int bid  = blockIdx.x;
    const int lane = tid & 31;
    const int wid  = tid >> 5;
    const int gtid = bid * NT + tid;

    // ============================ PHASE A0 ==================================
    // seg scatter + sense table + self-interaction + (block 0) weight transpose

    // A0a: segment starts via scatter on sorted pair_first
    for (int p = gtid; p < N_PAIRS; p += NB * NT) {
        int cur  = pf[p];
        int prev = (p == 0) ? -1 : pf[p - 1];
        for (int a = prev + 1; a <= cur; ++a) g_seg[a] = p;
        if (p == N_PAIRS - 1)
            for (int a = cur + 1; a <= N_ATOMS; ++a) g_seg[a] = N_PAIRS;
    }

    // A0b: sense table: sense[p][d] = cut(d_p) * exp(-0.5*((1/d - mu_d)/sg_d)^2)
    for (int p = gtid; p < N_PAIRS; p += NB * NT) {
        const float dd = dist[p];
        const float invd = 1.0f / dd;
        float cut = 0.f;
        if (dd < 6.5f) {
            float cc = cospif(dd * (0.5f / 6.5f));
            cut = cc * cc;
        }
        float* sp = g_sense + (size_t)p * 16;
#pragma unroll
        for (int d = 0; d < 16; ++d) {
            float t = (invd - __ldg(mu + d)) / __ldg(sg + d);
            sp[d] = cut * __expf(-0.5f * t * t);
        }
    }

    // A0c: block NB-1 builds the transposed fp16 weight table
    if (bid == NB - 1) {
        for (int idx = tid; idx < 32 * 256; idx += NT) {
            int f = idx >> 8, rem = idx & 255;
            int q = rem >> 5, o = rem & 31;
            float a = Wint[(2 * q) * (NF * NF) + o * NF + f];
            float b = Wint[(2 * q + 1) * (NF * NF) + o * NF + f];
            __half2 h2 = __floats2half2_rn(a, b);
            g_WT2[idx] = *reinterpret_cast<uint32_t*>(&h2);
        }
    }

    // A0d: self-interaction (fp32, via transposed smem weights)
    for (int i = tid; i < NF * NF; i += NT) {
        int o = i >> 5, f = i & 31;
        swT[f * NF + o] = sw[i];
    }
    __syncthreads();
    for (int idx = gtid; idx < N_ATOMS * NF; idx += NB * NT) {
        int a = idx >> 5, o = idx & 31;
        float s = sb[o];
        const float* fr = feat + (size_t)a * NF;
#pragma unroll
        for (int f = 0; f < NF; ++f)
            s = fmaf(fr[f], swT[f * NF + o], s);   // fr[f] warp-broadcast
        g_self[idx] = s;
    }

    grid_barrier();

    // ============================ PHASE A3 ==================================
    // A-table: A2[a, q*32+o] = half2( sum_f feat[a,f]*W[2q,o,f], ..W[2q+1..] )
    // col c = wid*32+lane = q*32+o; weight reads fully coalesced from g_WT2.
    {
        const int c = wid * 32 + lane;
        for (int tile = bid; tile < N_ATOMS / 8; tile += NB) {
            const int a0 = tile * 8;
            __syncthreads();
            fsh[tid] = feat[(size_t)a0 * NF + tid];
            __syncthreads();
            float accA[8], accB[8];
#pragma unroll
            for (int k = 0; k < 8; ++k) { accA[k] = 0.f; accB[k] = 0.f; }
#pragma unroll 8
            for (int f = 0; f < NF; ++f) {
                uint32_t w2 = g_WT2[f * 256 + c];
                float2 wf = __half22float2(*reinterpret_cast<__half2*>(&w2));
#pragma unroll
                for (int k = 0; k < 8; ++k) {
                    float fv = fsh[k * NF + f];
                    accA[k] = fmaf(fv, wf.x, accA[k]);
                    accB[k] = fmaf(fv, wf.y, accB[k]);
                }
            }
#pragma unroll
            for (int k = 0; k < 8; ++k) {
                __half2 h2 = __floats2half2_rn(accA[k], accB[k]);
                g_A2[(size_t)(a0 + k) * 256 + c] =
                    *reinterpret_cast<uint32_t*>(&h2);
            }
        }
    }

    grid_barrier();

    // ============================ PHASE B ===================================
    // warp per atom: lane = output channel o
    const int gwarp = bid * 8 + wid;

    for (int a = gwarp; a < N_ATOMS; a += NWARPS_TOT) {
        const int p0 = g_seg[a];
        const int n  = g_seg[a + 1] - p0;

        float acc0 = 0.f, acc1 = 0.f, acc2 = 0.f, acc3 = 0.f;

        if (n > 0) {
            int jn = (n > 1) ? psec[p0 + 1] : 0;
            uint32_t Ac[8];
            loadA(Ac, psec[p0], lane);

            for (int i = 0; i < n; ++i) {
                uint32_t An[8];
                if (i + 1 < n) loadA(An, jn, lane);       // jn from last iter
                int j2 = (i + 2 < n) ? psec[p0 + i + 2] : 0;

                const float4* sp = (const float4*)(g_sense + 16 * (size_t)(p0 + i));
                const float4 rh = *(const float4*)(rhats + 4 * (size_t)(p0 + i));

                // dot over 16 d: sense uniform float4s x fp16 A pairs, 2 chains
                float dA = 0.f, dB = 0.f;
#pragma unroll
                for (int g = 0; g < 4; ++g) {
                    float4 s = sp[g];
                    float2 a0 = __half22float2(*reinterpret_cast<__half2*>(&Ac[2 * g]));
                    float2 a1 = __half22float2(*reinterpret_cast<__half2*>(&Ac[2 * g + 1]));
                    dA = fmaf(s.x, a0.x, dA);
                    dB = fmaf(s.y, a0.y, dB);
                    dA = fmaf(s.z, a1.x, dA);
                    dB = fmaf(s.w, a1.y, dB);
                }
                const float wgt = dA + dB;
                acc0 = fmaf(rh.x, wgt, acc0);
                acc1 = fmaf(rh.y, wgt, acc1);
                acc2 = fmaf(rh.z, wgt, acc2);
                acc3 = fmaf(rh.w, wgt, acc3);

#pragma unroll
                for (int q = 0; q < 8; ++q) Ac[q] = An[q];
                jn = j2;
            }
        }

        // invariants
        const float inv0 = acc0;
        const float inv1 = acc1 * acc1 + acc2 * acc2 + acc3 * acc3;

        // GroupNorm over 32 lanes per group (two independent chains)
        const float m0 = warp_sum(inv0) * (1.f / 32.f);
        const float m1 = warp_sum(inv1) * (1.f / 32.f);
        const float c0 = inv0 - m0;
        const float c1 = inv1 - m1;
        const float v0s = warp_sum(c0 * c0) * (1.f / 32.f);
        const float v1s = warp_sum(c1 * c1) * (1.f / 32.f);
        float xn0 = c0 * rsqrtf(v0s + GN_EPS);
        float xn1 = c1 * rsqrtf(v1s + GN_EPS);
        xn0 = fmaf(xn0, gnw[lane], gnb[lane]);
        xn1 = fmaf(xn1, gnw[32 + lane], gnb[32 + lane]);

        // mixing + self (two accumulators for ILP)
        float oa = g_self[(size_t)a * NF + lane];
        float ob = 0.f;
#pragma unroll
        for (int oin = 0; oin < 32; ++oin) {
            const float n0 = __shfl_sync(0xffffffffu, xn0, oin);
            const float n1 = __shfl_sync(0xffffffffu, xn1, oin);
            oa = fmaf(n0, mw[(oin * 2 + 0) * NF + lane], oa);
            ob = fmaf(n1, mw[(oin * 2 + 1) * NF + lane], ob);
        }
        out[(size_t)a * NF + lane] = oa + ob;
    }
}

// ---------------------------------------------------------------------------
extern "C" void kernel_launch(void* const* d_in, const int* in_sizes, int n_in,
                              void* d_out, int out_size) {
    const float* in_features = (const float*)d_in[0];
    const float* tensor_rhats = (const float*)d_in[1];
    const float* dist_pairs = (const float*)d_in[2];
    const float* int_weights = (const float*)d_in[3];
    const float* selfint_w = (const float*)d_in[4];
    const float* selfint_b = (const float*)d_in[5];
    const float* mixing_weights = (const float*)d_in[6];
    const float* gn_weight = (const float*)d_in[7];
    const float* gn_bias = (const float*)d_in[8];
    const float* sens_mu = (const float*)d_in[9];
    const float* sens_sigma = (const float*)d_in[10];
    const int* pair_first = (const int*)d_in[11];
    const int* pair_second = (const int*)d_in[12];
    float* out = (float*)d_out;

    k_fused<<<NB, NT>>>(in_features, tensor_rhats, dist_pairs, int_weights,
                        selfint_w, selfint_b, mixing_weights, gn_weight,
                        gn_bias, sens_mu, sens_sigma, pair_first, pair_second,
                        out);
}